// round 9
// baseline (speedup 1.0000x reference)
#include <cuda_runtime.h>

#define NNZ     4194304
#define DENSE   16
#define DIMLOG  13
#define DIMSZ   8192
#define WORDS   2097152u           // 2^26 cells / 32
#define SCAN_BLOCKS 2048
#define SCAN_WPT 4
#define STAGE_CAP 4096
#define MAIN_BLOCKS (NNZ / 256)    // 32 rows/warp, 8 warps/block
#define TAIL_BLOCKS 256

// Compact mark-phase bits: x=occupancy, y=dup. Zero at entry (module init /
// re-zeroed by scatter tail blocks each run).
__device__ __align__(16) uint2 g_bits[WORDS];
// Scatter-phase metadata written by scan with full-line stores:
// x=occupancy bits, y=dup bits, z=exclusive slot offset of bit 0.
__device__ __align__(16) uint4 g_meta[WORDS];
__device__ unsigned g_desc[SCAN_BLOCKS];
__device__ unsigned g_ticket;
__device__ unsigned g_total;

// ---------------------------------------------------------------------------
__device__ __forceinline__ unsigned block_exscan(unsigned v, unsigned& blocktotal) {
    __shared__ unsigned warp_sums[8];
    __shared__ unsigned warp_off[8];
    unsigned lane = threadIdx.x & 31u, wid = threadIdx.x >> 5;
    unsigned x = v;
#pragma unroll
    for (int d = 1; d < 32; d <<= 1) {
        unsigned y = __shfl_up_sync(0xffffffffu, x, d);
        if ((int)lane >= d) x += y;
    }
    if (lane == 31) warp_sums[wid] = x;
    __syncthreads();
    if (threadIdx.x < 8) {
        unsigned s = warp_sums[threadIdx.x];
        unsigned inc = s;
#pragma unroll
        for (int d = 1; d < 8; d <<= 1) {
            unsigned y = __shfl_up_sync(0xffu, inc, d);
            if ((int)threadIdx.x >= d) inc += y;
        }
        warp_off[threadIdx.x] = inc - s;
    }
    __syncthreads();
    blocktotal = warp_off[7] + warp_sums[7];
    return warp_off[wid] + (x - v);
}

// ---------------------------------------------------------------------------
// B: mark occupancy + duplicate bits. 4 entries/thread, int4 loads.
// g_bits is guaranteed zero at entry (module init on first call; scatter's
// tail blocks re-zero it at the end of every run).
__global__ void k_mark(const int* __restrict__ idx) {
    unsigned i = blockIdx.x * 256u + threadIdx.x;
    int4 r = __ldcs((const int4*)idx + i);
    int4 c = __ldcs((const int4*)(idx + NNZ) + i);
    unsigned f[4] = {
        ((unsigned)r.x << DIMLOG) | (unsigned)c.x,
        ((unsigned)r.y << DIMLOG) | (unsigned)c.y,
        ((unsigned)r.z << DIMLOG) | (unsigned)c.z,
        ((unsigned)r.w << DIMLOG) | (unsigned)c.w };
#pragma unroll
    for (int j = 0; j < 4; j++) {
        unsigned w = f[j] >> 5, m = 1u << (f[j] & 31u);
        unsigned old = atomicOr(&g_bits[w].x, m);
        if (old & m) atomicOr(&g_bits[w].y, m);
    }
}

// S: single-pass scan (decoupled lookback) + full-line meta writes +
//    smem-staged compact of unique indices + dup-row zeroing + n_unique.
__global__ void k_scan_compact(float* __restrict__ out) {
    __shared__ unsigned sh_lbid, sh_prefix;
    __shared__ float s0[STAGE_CAP];
    __shared__ float s1[STAGE_CAP];
    unsigned tid = threadIdx.x;
    if (tid == 0) sh_lbid = atomicAdd(&g_ticket, 1u);
    __syncthreads();
    unsigned lbid = sh_lbid;
    unsigned base = lbid * (256u * SCAN_WPT) + tid * SCAN_WPT;

    uint2 bd[SCAN_WPT];
    unsigned s = 0;
#pragma unroll
    for (int j = 0; j < SCAN_WPT; j++) { bd[j] = g_bits[base + j]; s += __popc(bd[j].x); }
    unsigned tot;
    unsigned ex = block_exscan(s, tot);

    if (tid < 32) {
        if (tid == 0) atomicExch(&g_desc[lbid], (tot << 2) | (lbid == 0 ? 2u : 1u));
        unsigned prefix = 0;
        if (lbid > 0) {
            int look = (int)lbid - 1;
            unsigned running = 0;
            while (true) {
                int j = look - 31 + (int)tid;
                unsigned d;
                if (j < 0) d = 2u;
                else {
                    do { d = *((volatile unsigned*)(g_desc + j)); } while ((d & 3u) == 0u);
                }
                unsigned ball = __ballot_sync(0xffffffffu, (d & 3u) == 2u);
                if (ball) {
                    int hi = 31 - __clz(ball);
                    unsigned contrib = ((int)tid >= hi) ? (d >> 2) : 0u;
                    running += __reduce_add_sync(0xffffffffu, contrib);
                    break;
                } else {
                    running += __reduce_add_sync(0xffffffffu, d >> 2);
                    look -= 32;
                }
            }
            prefix = running;
            if (tid == 0) atomicExch(&g_desc[lbid], ((prefix + tot) << 2) | 2u);
        }
        if (tid == 0) sh_prefix = prefix;
    }
    __syncthreads();

    unsigned prefix = sh_prefix;
    unsigned off = prefix + ex;
    if (lbid == SCAN_BLOCKS - 1 && tid == 0) {
        unsigned nu = prefix + tot;
        g_total = nu;
        out[(size_t)2 * NNZ + (size_t)NNZ * DENSE] = (float)nu;
    }

    float* out0 = out;
    float* out1 = out + NNZ;
    float* vout = out + (size_t)2 * NNZ;
    bool staged = (tot <= STAGE_CAP);

#pragma unroll
    for (int j = 0; j < SCAN_WPT; j++) {
        unsigned w = base + j;
        unsigned bm = bd[j].x, dup = bd[j].y;
        uint4 m4; m4.x = bm; m4.y = dup; m4.z = off; m4.w = 0u;
        g_meta[w] = m4;                          // full-line STG.128
        unsigned o = off;
        unsigned v = bm;
        while (v) {
            unsigned b = (unsigned)__ffs(v) - 1u;
            v &= v - 1u;
            unsigned cell = (w << 5) | b;
            float rf = (float)(cell >> DIMLOG);
            float cf = (float)(cell & (DIMSZ - 1));
            if (staged) {
                unsigned lo = o - prefix;
                s0[lo] = rf; s1[lo] = cf;
            } else {
                __stcs(out0 + o, rf);
                __stcs(out1 + o, cf);
            }
            if ((dup >> b) & 1u) {
                float4* p = (float4*)(vout + (size_t)o * DENSE);
                float4 z = {0.f, 0.f, 0.f, 0.f};
                __stcs(p + 0, z); __stcs(p + 1, z); __stcs(p + 2, z); __stcs(p + 3, z);
            }
            o++;
        }
        off = o;
    }

    if (staged) {
        __syncthreads();
        for (unsigned i = tid; i < tot; i += 256u) {
            __stcs(out0 + prefix + i, s0[i]);
            __stcs(out1 + prefix + i, s1[i]);
        }
    }
}

// ---------------------------------------------------------------------------
// One 16-row value batch: (slot,dup) in packed, 2 float4s per thread.
__device__ __forceinline__ void move_rows(unsigned packed, unsigned rowIdx,
                                          unsigned sub,
                                          const float* __restrict__ vals,
                                          float* __restrict__ vout) {
    unsigned slot = packed >> 1, dup = packed & 1u;
    const float4* src = (const float4*)vals + (size_t)rowIdx * 4 + sub;
    float4 v0 = __ldcs(src + 0);
    float4 v1 = __ldcs(src + 1);
    float* dst = vout + (size_t)slot * DENSE + sub * 4;
    if (dup) {
        atomicAdd(dst + 0, v0.x); atomicAdd(dst + 1, v0.y);
        atomicAdd(dst + 2, v0.z); atomicAdd(dst + 3, v0.w);
        atomicAdd(dst + 4, v1.x); atomicAdd(dst + 5, v1.y);
        atomicAdd(dst + 6, v1.z); atomicAdd(dst + 7, v1.w);
    } else {
        __stcs((float4*)dst + 0, v0);
        __stcs((float4*)dst + 1, v1);
    }
}

// E: scatter values. 32 rows/warp: EVERY lane resolves one row's (slot,dup)
// -> 32 random meta loads in flight per warp. Then two 16-row batches move
// values (4 independent LDG.128 + 4 STG.128 per thread). Tail blocks fill
// padding and reset g_bits/g_desc/g_ticket for the next run.
__global__ void k_scatter(const int* __restrict__ idx,
                          const float* __restrict__ vals,
                          float* __restrict__ out) {
    float* vout = out + (size_t)2 * NNZ;

    if (blockIdx.x >= MAIN_BLOCKS) {
        unsigned tb = blockIdx.x - MAIN_BLOCKS;
        unsigned t0 = tb * 256u + threadIdx.x;
        // (a) padded tail: indices (8192, 0), zero values
        unsigned nu = g_total;
        float4 z4 = {0.f, 0.f, 0.f, 0.f};
        for (unsigned slot = nu + t0; slot < NNZ; slot += TAIL_BLOCKS * 256u) {
            __stcs(out + slot, 8192.0f);
            __stcs(out + NNZ + slot, 0.0f);
            float4* v = (float4*)(vout + (size_t)slot * DENSE);
            __stcs(v + 0, z4); __stcs(v + 1, z4); __stcs(v + 2, z4); __stcs(v + 3, z4);
        }
        // (b) reset mark bits for the next run (g_bits is dead after scan)
        uint4 z = {0u, 0u, 0u, 0u};
        for (unsigned i = t0; i < WORDS / 2; i += TAIL_BLOCKS * 256u)
            __stcs(((uint4*)g_bits) + i, z);
        // (c) reset lookback descriptors + ticket
        if (tb == 0) {
            if (threadIdx.x < SCAN_BLOCKS / 4) ((uint4*)g_desc)[threadIdx.x] = z;
            if (threadIdx.x == 0) g_ticket = 0u;
        }
        return;
    }

    unsigned t = blockIdx.x * 256u + threadIdx.x;
    unsigned lane = threadIdx.x & 31u;
    unsigned warpRow0 = (t >> 5) * 32u;

    // Every lane resolves one row: coalesced idx loads, 32 meta loads in flight.
    unsigned r = warpRow0 + lane;
    unsigned flat = ((unsigned)__ldg(idx + r) << DIMLOG) | (unsigned)__ldg(idx + NNZ + r);
    unsigned w = flat >> 5, b = flat & 31u;
    uint4 mt = __ldg(&g_meta[w]);
    unsigned slot = mt.z + __popc(mt.x & ((1u << b) - 1u));
    unsigned packed = (slot << 1) | ((mt.y >> b) & 1u);

    // Batch A: rows warpRow0+0..15 ; Batch B: rows warpRow0+16..31.
    unsigned pA = __shfl_sync(0xffffffffu, packed, lane >> 1);
    unsigned pB = __shfl_sync(0xffffffffu, packed, 16u + (lane >> 1));
    unsigned sub = (lane & 1u) * 2u;
    unsigned iA = warpRow0 + (lane >> 1);
    unsigned iB = iA + 16u;

    move_rows(pA, iA, sub, vals, vout);
    move_rows(pB, iB, sub, vals, vout);
}

// ---------------------------------------------------------------------------
extern "C" void kernel_launch(void* const* d_in, const int* in_sizes, int n_in,
                              void* d_out, int out_size) {
    (void)in_sizes; (void)n_in; (void)out_size;
    const int*   idx  = (const int*)d_in[0];
    const float* vals = (const float*)d_in[1];
    float* out = (float*)d_out;

    k_mark        <<<NNZ / 4 / 256, 256>>>(idx);
    k_scan_compact<<<SCAN_BLOCKS,   256>>>(out);
    k_scatter     <<<MAIN_BLOCKS + TAIL_BLOCKS, 256>>>(idx, vals, out);
}